// round 11
// baseline (speedup 1.0000x reference)
#include <cuda_runtime.h>
#include <cuda_fp16.h>
#include <cstdint>
#include <cstddef>

// Problem constants
#define B_   2
#define S_   2048
#define D_   1024
#define H_   16
#define DH_  64
#define BS_  (B_ * S_)            // 4096
#define QKV_N (3 * D_)            // 3072
#define OUT_ATTN_ELEMS ((size_t)BS_ * D_)           // 4,194,304

// Scratch (allocation-free rule: __device__ globals)
__device__ float g_qkv[BS_ * QKV_N];   // [4096, 3072] : Q | K | V packed (fp32)
__device__ float g_mx[B_ * H_ * S_];   // per-row softmax max
__device__ float g_inv[B_ * H_ * S_];  // per-row 1/sum
// fp16 split operands for the dense GEMMs
__device__ __half g_ahi[BS_ * D_];
__device__ __half g_alo[BS_ * D_];
__device__ __half g_w1h[QKV_N * D_];   // c_attn_w^T [3072,1024] fp16
__device__ __half g_w2h[D_ * D_];      // c_proj_w^T [1024,1024] fp16

// ===========================================================================
// HMMA / async-copy helpers
// ===========================================================================
__device__ __forceinline__ uint32_t smem_u32(const void* p) {
    uint32_t a;
    asm("{ .reg .u64 t; cvta.to.shared.u64 t, %1; cvt.u32.u64 %0, t; }"
        : "=r"(a) : "l"(p));
    return a;
}

__device__ __forceinline__ void ldm_x4(uint32_t r[4], uint32_t saddr) {
    asm volatile("ldmatrix.sync.aligned.m8n8.x4.shared.b16 {%0,%1,%2,%3}, [%4];"
                 : "=r"(r[0]), "=r"(r[1]), "=r"(r[2]), "=r"(r[3]) : "r"(saddr));
}

__device__ __forceinline__ void mma_f16(float c[4], const uint32_t a[4],
                                        const uint32_t b[2]) {
    asm volatile(
        "mma.sync.aligned.m16n8k16.row.col.f32.f16.f16.f32 "
        "{%0,%1,%2,%3}, {%4,%5,%6,%7}, {%8,%9}, {%0,%1,%2,%3};"
        : "+f"(c[0]), "+f"(c[1]), "+f"(c[2]), "+f"(c[3])
        : "r"(a[0]), "r"(a[1]), "r"(a[2]), "r"(a[3]), "r"(b[0]), "r"(b[1]));
}

__device__ __forceinline__ void cp16(uint32_t saddr, const void* gaddr) {
    asm volatile("cp.async.ca.shared.global [%0], [%1], 16;"
                 :: "r"(saddr), "l"(gaddr));
}
#define CP_COMMIT() asm volatile("cp.async.commit_group;" ::: "memory")
#define CP_WAIT(N)  asm volatile("cp.async.wait_group %0;" :: "n"(N) : "memory")

// Split a float4 into fp16 hi/lo (8B each).
__device__ __forceinline__ void split4h(float4 v, __half* hp, __half* lp)
{
    __half2 h0, h1, l0, l1;
    h0.x = __float2half_rn(v.x); h0.y = __float2half_rn(v.y);
    h1.x = __float2half_rn(v.z); h1.y = __float2half_rn(v.w);
    l0.x = __float2half_rn(v.x - __half2float(h0.x));
    l0.y = __float2half_rn(v.y - __half2float(h0.y));
    l1.x = __float2half_rn(v.z - __half2float(h1.x));
    l1.y = __float2half_rn(v.w - __half2float(h1.y));
    uint2 hu, lu;
    hu.x = *reinterpret_cast<uint32_t*>(&h0);
    hu.y = *reinterpret_cast<uint32_t*>(&h1);
    lu.x = *reinterpret_cast<uint32_t*>(&l0);
    lu.y = *reinterpret_cast<uint32_t*>(&l1);
    *reinterpret_cast<uint2*>(hp) = hu;
    *reinterpret_cast<uint2*>(lp) = lu;
}

// Convert a float4 to 4 fp16 (single 8B store).
__device__ __forceinline__ void conv4h(float4 v, __half* p)
{
    __half2 h0, h1;
    h0.x = __float2half_rn(v.x); h0.y = __float2half_rn(v.y);
    h1.x = __float2half_rn(v.z); h1.y = __float2half_rn(v.w);
    uint2 hu;
    hu.x = *reinterpret_cast<uint32_t*>(&h0);
    hu.y = *reinterpret_cast<uint32_t*>(&h1);
    *reinterpret_cast<uint2*>(p) = hu;
}

// ===========================================================================
// Split kernels
// ===========================================================================
__global__ __launch_bounds__(256)
void split_rows_kernel(const float* __restrict__ in,
                       __half* __restrict__ hi,
                       __half* __restrict__ lo, int n4)
{
    int i = blockIdx.x * 256 + threadIdx.x;
    if (i >= n4) return;
    float4 v = reinterpret_cast<const float4*>(in)[i];
    split4h(v, hi + i * 4, lo + i * 4);
}

// Transpose + convert: in [K,N] fp32 -> out [N,K] fp16
__global__ __launch_bounds__(256)
void conv_T_kernel(const float* __restrict__ in,
                   __half* __restrict__ hi, int K, int N)
{
    __shared__ float t[32][33];
    int n0 = blockIdx.x * 32, k0 = blockIdx.y * 32;
    int tx = threadIdx.x & 31, ty = threadIdx.x >> 5;   // 32 x 8
#pragma unroll
    for (int i = 0; i < 4; i++)
        t[ty + 8 * i][tx] = in[(size_t)(k0 + ty + 8 * i) * N + n0 + tx];
    __syncthreads();
#pragma unroll
    for (int i = 0; i < 4; i++) {
        float v = t[tx][ty + 8 * i];
        hi[(size_t)(n0 + ty + 8 * i) * K + k0 + tx] = __float2half_rn(v);
    }
}

// ===========================================================================
// cp.async double-buffered HMMA GEMM (fp16, 2-pass):
// C[M,N] = (Ahi+Alo)[M,K] @ B[N,K]^T + bias[N]
// ===========================================================================
#define SPAD    40
#define TILE_E  (128 * SPAD)
#define STAGE_E (3 * TILE_E)          // Ahi, Alo, B
#define GEMM_SMEM_BYTES (2 * STAGE_E * 2)

__device__ __forceinline__ void gemm_issue_loads(
    const __half* __restrict__ Ahi, const __half* __restrict__ Alo,
    const __half* __restrict__ B,
    uint32_t sm_base, int stage, int row0, int col0, int kk, int K, int tid)
{
    const uint32_t st = sm_base + (uint32_t)stage * STAGE_E * 2;
#pragma unroll
    for (int u = 0; u < 2; u++) {
        int s  = tid + u * 256;
        int r  = s >> 2;
        int cg = (s & 3) * 8;
        size_t goffA = (size_t)(row0 + r) * K + kk + cg;
        size_t goffB = (size_t)(col0 + r) * K + kk + cg;
        uint32_t so = (uint32_t)(r * SPAD + cg) * 2;
        cp16(st + 0 * TILE_E * 2 + so, Ahi + goffA);
        cp16(st + 1 * TILE_E * 2 + so, Alo + goffA);
        cp16(st + 2 * TILE_E * 2 + so, B + goffB);
    }
}

__global__ __launch_bounds__(256, 2)
void gemm_hmma_async(const __half* __restrict__ Ahi,
                     const __half* __restrict__ Alo,
                     const __half* __restrict__ B,
                     const float* __restrict__ bias,
                     float* __restrict__ C, int M, int N, int K)
{
    extern __shared__ __half sm[];
    const uint32_t sm_base = smem_u32(sm);

    const int tid  = threadIdx.x;
    const int lane = tid & 31;
    const int warp = tid >> 5;
    const int row0 = blockIdx.y * 128;
    const int col0 = blockIdx.x * 128;
    const int warp_m = (warp & 3) * 32;
    const int warp_n = (warp >> 2) * 64;

    float acc[2][8][4];
#pragma unroll
    for (int i = 0; i < 2; i++)
#pragma unroll
        for (int j = 0; j < 8; j++)
#pragma unroll
            for (int r = 0; r < 4; r++) acc[i][j][r] = 0.0f;

    const int a_r = warp_m + (lane & 15);
    const int a_c = (lane >> 4) * 8;
    const int b_r = warp_n + (lane & 7) + (lane >> 4) * 8;
    const int b_c = ((lane >> 3) & 1) * 8;

    const int nch = K >> 5;

    gemm_issue_loads(Ahi, Alo, B, sm_base, 0, row0, col0, 0, K, tid);
    CP_COMMIT();

    for (int c = 0; c < nch; c++) {
        const int cur = c & 1;
        if (c + 1 < nch) {
            gemm_issue_loads(Ahi, Alo, B, sm_base, cur ^ 1,
                             row0, col0, (c + 1) << 5, K, tid);
            CP_COMMIT();
            CP_WAIT(1);
        } else {
            CP_WAIT(0);
        }
        __syncthreads();

        const __half* sAhi = sm + cur * STAGE_E + 0 * TILE_E;
        const __half* sAlo = sm + cur * STAGE_E + 1 * TILE_E;
        const __half* sB   = sm + cur * STAGE_E + 2 * TILE_E;

#pragma unroll
        for (int ks = 0; ks < 32; ks += 16) {
            uint32_t a_h[2][4], a_l[2][4];
            uint32_t b_f[8][2];
#pragma unroll
            for (int i = 0; i < 2; i++) {
                int el = (a_r + i * 16) * SPAD + ks + a_c;
                ldm_x4(a_h[i], smem_u32(sAhi + el));
                ldm_x4(a_l[i], smem_u32(sAlo + el));
            }
#pragma unroll
            for (int jj = 0; jj < 4; jj++) {
                int el = (b_r + jj * 16) * SPAD + ks + b_c;
                ldm_x4(&b_f[jj * 2][0], smem_u32(sB + el));
            }
#pragma unroll
            for (int i = 0; i < 2; i++)
#pragma unroll
                for (int j = 0; j < 8; j++)
                    mma_f16(acc[i][j], a_h[i], b_f[j]);
#pragma unroll
            for (int i = 0; i < 2; i++)
#pragma unroll
                for (int j = 0; j < 8; j++)
                    mma_f16(acc[i][j], a_l[i], b_f[j]);
        }
        __syncthreads();
    }

#pragma unroll
    for (int i = 0; i < 2; i++) {
#pragma unroll
        for (int j = 0; j < 8; j++) {
            int m = row0 + warp_m + i * 16 + (lane >> 2);
            int n = col0 + warp_n + j * 8 + (lane & 3) * 2;
            float2 bz = *reinterpret_cast<const float2*>(&bias[n]);
            float2 o0; o0.x = acc[i][j][0] + bz.x; o0.y = acc[i][j][1] + bz.y;
            float2 o1; o1.x = acc[i][j][2] + bz.x; o1.y = acc[i][j][3] + bz.y;
            *reinterpret_cast<float2*>(&C[(size_t)m * N + n]) = o0;
            *reinterpret_cast<float2*>(&C[(size_t)(m + 8) * N + n]) = o1;
        }
    }
}

// ===========================================================================
// Scores on HMMA (fp16 2-pass): raw scaled scores, lower-triangle tiles only.
// Masked lanes in diagonal tiles get 0.0 (never read downstream).
// ===========================================================================
__global__ __launch_bounds__(256)
void scores_hmma_kernel(float* __restrict__ W)
{
    __shared__ __half sQh[128 * SPAD];
    __shared__ __half sQl[128 * SPAD];
    __shared__ __half sKh[128 * SPAD];

    const int tid  = threadIdx.x;
    const int lane = tid & 31;
    const int warp = tid >> 5;
    const int bh   = blockIdx.y;
    const int b    = bh >> 4;
    const int h    = bh & 15;

    int pair = blockIdx.x;
    int qt = (int)((-1.0f + sqrtf(1.0f + 8.0f * (float)pair)) * 0.5f);
    while ((qt + 1) * (qt + 2) / 2 <= pair) ++qt;
    while (qt * (qt + 1) / 2 > pair) --qt;
    const int kt = pair - qt * (qt + 1) / 2;

    const int q0 = qt * 128;
    const int k0 = kt * 128;
    const int warp_m = (warp & 3) * 32;
    const int warp_n = (warp >> 2) * 64;

    float acc[2][8][4];
#pragma unroll
    for (int i = 0; i < 2; i++)
#pragma unroll
        for (int j = 0; j < 8; j++)
#pragma unroll
            for (int r = 0; r < 4; r++) acc[i][j][r] = 0.0f;

    const int a_r = warp_m + (lane & 15);
    const int a_c = (lane >> 4) * 8;
    const int b_r = warp_n + (lane & 7) + (lane >> 4) * 8;
    const int b_c = ((lane >> 3) & 1) * 8;

    const size_t qbase = (size_t)(b * S_ + q0) * QKV_N + h * DH_;
    const size_t kbase = (size_t)(b * S_ + k0) * QKV_N + D_ + h * DH_;

    const int lr = tid >> 1;
    const int lc0 = (tid & 1) * 16;

    for (int dc = 0; dc < DH_; dc += 32) {
#pragma unroll
        for (int i = 0; i < 4; i++) {
            int c = lc0 + i * 4;
            float4 vq = *reinterpret_cast<const float4*>(
                &g_qkv[qbase + (size_t)lr * QKV_N + dc + c]);
            float4 vk = *reinterpret_cast<const float4*>(
                &g_qkv[kbase + (size_t)lr * QKV_N + dc + c]);
            split4h(vq, &sQh[lr * SPAD + c], &sQl[lr * SPAD + c]);
            conv4h(vk, &sKh[lr * SPAD + c]);
        }
        __syncthreads();

#pragma unroll
        for (int ks = 0; ks < 32; ks += 16) {
            uint32_t a_h[2][4], a_l[2][4];
            uint32_t b_f[8][2];
#pragma unroll
            for (int i = 0; i < 2; i++) {
                int el = (a_r + i * 16) * SPAD + ks + a_c;
                ldm_x4(a_h[i], smem_u32(&sQh[el]));
                ldm_x4(a_l[i], smem_u32(&sQl[el]));
            }
#pragma unroll
            for (int jj = 0; jj < 4; jj++) {
                int el = (b_r + jj * 16) * SPAD + ks + b_c;
                ldm_x4(&b_f[jj * 2][0], smem_u32(&sKh[el]));
            }
#pragma unroll
            for (int i = 0; i < 2; i++)
#pragma unroll
                for (int j = 0; j < 8; j++)
                    mma_f16(acc[i][j], a_h[i], b_f[j]);
#pragma unroll
            for (int i = 0; i < 2; i++)
#pragma unroll
                for (int j = 0; j < 8; j++)
                    mma_f16(acc[i][j], a_l[i], b_f[j]);
        }
        __syncthreads();
    }

    float* Wbh = W + (size_t)bh * S_ * S_;
#pragma unroll
    for (int i = 0; i < 2; i++) {
#pragma unroll
        for (int j = 0; j < 8; j++) {
            int q  = q0 + warp_m + i * 16 + (lane >> 2);
            int k  = k0 + warp_n + j * 8 + (lane & 3) * 2;
            float2 o0, o1;
            o0.x = (k     > q) ? 0.0f : acc[i][j][0] * 0.125f;
            o0.y = (k + 1 > q) ? 0.0f : acc[i][j][1] * 0.125f;
            o1.x = (k     > q + 8) ? 0.0f : acc[i][j][2] * 0.125f;
            o1.y = (k + 1 > q + 8) ? 0.0f : acc[i][j][3] * 0.125f;
            *reinterpret_cast<float2*>(&Wbh[(size_t)q * S_ + k]) = o0;
            *reinterpret_cast<float2*>(&Wbh[(size_t)(q + 8) * S_ + k]) = o1;
        }
    }
}

// ---------------------------------------------------------------------------
// Stats: per-row max + 1/sum of exp over the valid (causal) region.
// No weight stores — normalize happens inside AV.
// ---------------------------------------------------------------------------
__global__ __launch_bounds__(256)
void stats_kernel(const float* __restrict__ W)
{
    const int tid = threadIdx.x;
    const int lane = tid & 31;
    const int warp = tid >> 5;
    const int row = blockIdx.x;
    const int q = row & (S_ - 1);
    const int nvalid = q + 1;
    const float* w = W + (size_t)row * S_;

    __shared__ float red[8];

    float4 v[2];
    float m = -1e30f;
#pragma unroll
    for (int r = 0; r < 2; r++) {
        int k0 = (r * 256 + tid) * 4;
        float4 x;
        if (k0 < nvalid) {
            x = *reinterpret_cast<const float4*>(w + k0);
            x.x = (k0 + 0 < nvalid) ? x.x : -1e30f;
            x.y = (k0 + 1 < nvalid) ? x.y : -1e30f;
            x.z = (k0 + 2 < nvalid) ? x.z : -1e30f;
            x.w = (k0 + 3 < nvalid) ? x.w : -1e30f;
        } else {
            x.x = x.y = x.z = x.w = -1e30f;
        }
        v[r] = x;
        m = fmaxf(m, fmaxf(fmaxf(x.x, x.y), fmaxf(x.z, x.w)));
    }
#pragma unroll
    for (int off = 16; off > 0; off >>= 1)
        m = fmaxf(m, __shfl_xor_sync(0xFFFFFFFFu, m, off));
    if (lane == 0) red[warp] = m;
    __syncthreads();
    float mx = red[0];
#pragma unroll
    for (int i = 1; i < 8; i++) mx = fmaxf(mx, red[i]);
    __syncthreads();

    float s = 0.0f;
#pragma unroll
    for (int r = 0; r < 2; r++) {
        int k0 = (r * 256 + tid) * 4;
        float4 x = v[r];
        s += (k0 + 0 < nvalid) ? __expf(x.x - mx) : 0.0f;
        s += (k0 + 1 < nvalid) ? __expf(x.y - mx) : 0.0f;
        s += (k0 + 2 < nvalid) ? __expf(x.z - mx) : 0.0f;
        s += (k0 + 3 < nvalid) ? __expf(x.w - mx) : 0.0f;
    }
#pragma unroll
    for (int off = 16; off > 0; off >>= 1)
        s += __shfl_xor_sync(0xFFFFFFFFu, s, off);
    if (lane == 0) red[warp] = s;
    __syncthreads();

    if (tid == 0) {
        float tot = red[0];
#pragma unroll
        for (int i = 1; i < 8; i++) tot += red[i];
        g_mx[row]  = mx;
        g_inv[row] = 1.0f / tot;
    }
}

// ===========================================================================
// AV fused (fp16 2-pass): reads RAW scores, normalizes in-register using
// g_mx/g_inv, writes FINAL weights (incl. zero upper region), and runs the
// AV HMMA in the same pass. Final-W stores hide under MMA compute.
// ===========================================================================
__global__ __launch_bounds__(256)
void av_hmma_kernel(float* __restrict__ W)
{
    __shared__ __half sWh[128 * SPAD];
    __shared__ __half sWl[128 * SPAD];
    __shared__ __half sVh[64 * SPAD];

    const int tid  = threadIdx.x;
    const int lane = tid & 31;
    const int warp = tid >> 5;
    const int bh   = blockIdx.y;
    const int b    = bh >> 4;
    const int h    = bh & 15;
    const int qblk = blockIdx.x;
    const int q0   = qblk * 128;
    const int warp_m = warp * 16;

    float* Wbh = W + (size_t)bh * S_ * S_;
    const size_t vbase = (size_t)b * S_ * QKV_N + 2 * D_ + h * DH_;

    float acc[8][4];
#pragma unroll
    for (int j = 0; j < 8; j++)
#pragma unroll
        for (int r = 0; r < 4; r++) acc[j][r] = 0.0f;

    const int a_r = warp_m + (lane & 15);
    const int a_c = (lane >> 4) * 8;
    const int b_r = (lane & 7) + (lane >> 4) * 8;
    const int b_c = ((lane >> 3) & 1) * 8;

    const int wr  = tid >> 1;
    const int wc0 = (tid & 1) * 16;
    const int vd  = tid & 63;
    const int vk0 = (tid >> 6) * 8;

    const int qg = q0 + wr;
    const float mx_r  = g_mx[bh * S_ + qg];
    const float inv_r = g_inv[bh * S_ + qg];

    const int nch = (qblk + 1) * 4;
    for (int t = 0; t < nch; t++) {
        const int kc = t * 32;
        // load raw scores, normalize (exact 0 above diagonal), write final W,
        // split into sWh/sWl
#pragma unroll
        for (int i = 0; i < 4; i++) {
            int c  = wc0 + i * 4;
            int kg = kc + c;
            float4 v = *reinterpret_cast<const float4*>(
                &Wbh[(size_t)qg * S_ + kg]);
            v.x = (kg     <= qg) ? __expf(v.x - mx_r) * inv_r : 0.0f;
            v.y = (kg + 1 <= qg) ? __expf(v.y - mx_r) * inv_r : 0.0f;
            v.z = (kg + 2 <= qg) ? __expf(v.z - mx_r) * inv_r : 0.0f;
            v.w = (kg + 3 <= qg) ? __expf(v.w - mx_r) * inv_r : 0.0f;
            *reinterpret_cast<float4*>(&Wbh[(size_t)qg * S_ + kg]) = v;
            split4h(v, &sWh[wr * SPAD + c], &sWl[wr * SPAD + c]);
        }
        // load + convert + transpose V tile [32 x 64] -> sVh [d][k]
        {
            uint32_t hp[4];
#pragma unroll
            for (int i = 0; i < 4; i++) {
                float x0 = g_qkv[vbase + (size_t)(kc + vk0 + 2 * i) * QKV_N + vd];
                float x1 = g_qkv[vbase + (size_t)(kc + vk0 + 2 * i + 1) * QKV_N + vd];
                __half2 hh;
                hh.x = __float2half_rn(x0); hh.y = __float2half_rn(x1);
                hp[i] = *reinterpret_cast<uint32_t*>(&hh);
            }
            uint4 hv; hv.x = hp[0]; hv.y = hp[1]; hv.z = hp[2]; hv.w = hp[3];
            *reinterpret_cast<uint4*>(&sVh[vd * SPAD + vk0]) = hv;
        }
        __syncthreads();

#pragma unroll
        for (int ks = 0; ks < 32; ks += 16) {
            uint32_t a_h[4], a_l[4];
            uint32_t b_f[8][2];
            {
                int el = a_r * SPAD + ks + a_c;
                ldm_x4(a_h, smem_u32(&sWh[el]));
                ldm_x4(a_l, smem_u32(&sWl[el]));
            }
#pragma unroll
            for (int jj = 0; jj < 4; jj++) {
                int el = (b_r + jj * 16) * SPAD + ks + b_c;
                ldm_x4(&b_f[jj * 2][0], smem_u32(&sVh[el]));
            }
#pragma unroll
            for (int j = 0; j < 8; j++)
                mma_f16(acc[j], a_h, b_f[j]);
#pragma unroll
            for (int j = 0; j < 8; j++)
                mma_f16(acc[j], a_l, b_f[j]);
        }
        __syncthreads();
    }

    // zero-fill the untouched upper region of this q-block's rows
    {
        const int c0 = (qblk + 1) * 128;
        if (c0 < S_) {
            const int f4_per_row = (S_ - c0) >> 2;
            const int total = 128 * f4_per_row;
            float4 z; z.x = 0.0f; z.y = 0.0f; z.z = 0.0f; z.w = 0.0f;
            for (int idx = tid; idx < total; idx += 256) {
                int r  = idx / f4_per_row;
                int cc = c0 + (idx - r * f4_per_row) * 4;
                *reinterpret_cast<float4*>(&Wbh[(size_t)(q0 + r) * S_ + cc]) = z;
            }
        }
    }

    // epilogue: split to fp16 hi/lo and write g_ahi/g_alo directly
#pragma unroll
    for (int j = 0; j < 8; j++) {
        int m = q0 + warp_m + (lane >> 2);
        int n = j * 8 + (lane & 3) * 2;
        size_t o0 = (size_t)(b * S_ + m) * D_ + h * DH_ + n;
        size_t o1 = (size_t)(b * S_ + m + 8) * D_ + h * DH_ + n;
        __half2 h0, l0, h1, l1;
        h0.x = __float2half_rn(acc[j][0]);
        h0.y = __float2half_rn(acc[j][1]);
        l0.x = __float2half_rn(acc[j][0] - __half2float(h0.x));
        l0.y = __float2half_rn(acc[j][1] - __half2float(h0.y));
        h1.x = __float2half_rn(acc[j][2]);
        h1.y = __float2half_rn(acc[j][3]);
        l1.x = __float2half_rn(acc[j][2] - __half2float(h1.x));
        l1.y = __float2half_rn(acc[j][3] - __half2float(h1.y));
        *reinterpret_cast<__half2*>(&g_ahi[o0]) = h0;
        *reinterpret_cast<__half2*>(&g_alo[o0]) = l0;
        *reinterpret_cast<__half2*>(&g_ahi[o1]) = h1;
        *reinterpret_cast<__half2*>(&g_alo[o1]) = l1;
    }
}

// ---------------------------------------------------------------------------
extern "C" void kernel_launch(void* const* d_in, const int* in_sizes, int n_in,
                              void* d_out, int out_size)
{
    const float* hs       = (const float*)d_in[0];
    const float* c_attn_w = (const float*)d_in[1];
    const float* c_attn_b = (const float*)d_in[2];
    const float* c_proj_w = (const float*)d_in[3];
    const float* c_proj_b = (const float*)d_in[4];

    float* out  = (float*)d_out;
    float* Wout = out + OUT_ATTN_ELEMS;

    float *qkv_ptr = nullptr;
    __half *ahi, *alo, *w1h, *w2h;
    cudaGetSymbolAddress((void**)&qkv_ptr, g_qkv);
    cudaGetSymbolAddress((void**)&ahi, g_ahi);
    cudaGetSymbolAddress((void**)&alo, g_alo);
    cudaGetSymbolAddress((void**)&w1h, g_w1h);
    cudaGetSymbolAddress((void**)&w2h, g_w2h);

    static bool attr_set = false;
    if (!attr_set) {
        cudaFuncSetAttribute(gemm_hmma_async,
                             cudaFuncAttributeMaxDynamicSharedMemorySize,
                             GEMM_SMEM_BYTES);
        attr_set = true;
    }

    // 0) splits/conversions for dense GEMMs
    split_rows_kernel<<<(BS_ * D_ / 4 + 255) / 256, 256>>>(hs, ahi, alo, BS_ * D_ / 4);
    conv_T_kernel<<<dim3(QKV_N / 32, D_ / 32), 256>>>(c_attn_w, w1h, D_, QKV_N);
    conv_T_kernel<<<dim3(D_ / 32, D_ / 32), 256>>>(c_proj_w, w2h, D_, D_);

    // 1) QKV GEMM (HMMA fp16 2-pass, cp.async pipelined)
    gemm_hmma_async<<<dim3(QKV_N / 128, BS_ / 128), 256, GEMM_SMEM_BYTES>>>(
        ahi, alo, w1h, c_attn_b, qkv_ptr, BS_, QKV_N, D_);

    // 2) Scores (raw, lower-triangle tiles only — balanced grid)
    scores_hmma_kernel<<<dim3(136, B_ * H_), 256>>>(Wout);

    // 3) Stats (row max + 1/sum; no stores to W)
    stats_kernel<<<B_ * H_ * S_, 256>>>(Wout);

    // 4) AV fused: normalize + final-W write + zero-fill + AV HMMA
    av_hmma_kernel<<<dim3(S_ / 128, B_ * H_), 256>>>(Wout);

    // 5) proj GEMM (HMMA fp16 2-pass) — consumes g_ahi/g_alo from AV
    gemm_hmma_async<<<dim3(D_ / 128, BS_ / 128), 256, GEMM_SMEM_BYTES>>>(
        ahi, alo, w2h, c_proj_b, out, BS_, D_, D_);
}

// round 12
// speedup vs baseline: 2.7601x; 2.7601x over previous
#include <cuda_runtime.h>
#include <cuda_fp16.h>
#include <cstdint>
#include <cstddef>

// Problem constants
#define B_   2
#define S_   2048
#define D_   1024
#define H_   16
#define DH_  64
#define BS_  (B_ * S_)            // 4096
#define QKV_N (3 * D_)            // 3072
#define OUT_ATTN_ELEMS ((size_t)BS_ * D_)           // 4,194,304

// Scratch (allocation-free rule: __device__ globals)
__device__ float g_qkv[BS_ * QKV_N];   // [4096, 3072] : Q | K | V packed (fp32)
// fp16 split operands for the dense GEMMs
__device__ __half g_ahi[BS_ * D_];
__device__ __half g_alo[BS_ * D_];
__device__ __half g_w1h[QKV_N * D_];   // c_attn_w^T [3072,1024] fp16
__device__ __half g_w2h[D_ * D_];      // c_proj_w^T [1024,1024] fp16

// ===========================================================================
// HMMA / async-copy helpers
// ===========================================================================
__device__ __forceinline__ uint32_t smem_u32(const void* p) {
    uint32_t a;
    asm("{ .reg .u64 t; cvta.to.shared.u64 t, %1; cvt.u32.u64 %0, t; }"
        : "=r"(a) : "l"(p));
    return a;
}

__device__ __forceinline__ void ldm_x4(uint32_t r[4], uint32_t saddr) {
    asm volatile("ldmatrix.sync.aligned.m8n8.x4.shared.b16 {%0,%1,%2,%3}, [%4];"
                 : "=r"(r[0]), "=r"(r[1]), "=r"(r[2]), "=r"(r[3]) : "r"(saddr));
}

__device__ __forceinline__ void mma_f16(float c[4], const uint32_t a[4],
                                        const uint32_t b[2]) {
    asm volatile(
        "mma.sync.aligned.m16n8k16.row.col.f32.f16.f16.f32 "
        "{%0,%1,%2,%3}, {%4,%5,%6,%7}, {%8,%9}, {%0,%1,%2,%3};"
        : "+f"(c[0]), "+f"(c[1]), "+f"(c[2]), "+f"(c[3])
        : "r"(a[0]), "r"(a[1]), "r"(a[2]), "r"(a[3]), "r"(b[0]), "r"(b[1]));
}

__device__ __forceinline__ void cp16(uint32_t saddr, const void* gaddr) {
    asm volatile("cp.async.ca.shared.global [%0], [%1], 16;"
                 :: "r"(saddr), "l"(gaddr));
}
#define CP_COMMIT() asm volatile("cp.async.commit_group;" ::: "memory")
#define CP_WAIT(N)  asm volatile("cp.async.wait_group %0;" :: "n"(N) : "memory")

// Split a float4 into fp16 hi/lo (8B each).
__device__ __forceinline__ void split4h(float4 v, __half* hp, __half* lp)
{
    __half2 h0, h1, l0, l1;
    h0.x = __float2half_rn(v.x); h0.y = __float2half_rn(v.y);
    h1.x = __float2half_rn(v.z); h1.y = __float2half_rn(v.w);
    l0.x = __float2half_rn(v.x - __half2float(h0.x));
    l0.y = __float2half_rn(v.y - __half2float(h0.y));
    l1.x = __float2half_rn(v.z - __half2float(h1.x));
    l1.y = __float2half_rn(v.w - __half2float(h1.y));
    uint2 hu, lu;
    hu.x = *reinterpret_cast<uint32_t*>(&h0);
    hu.y = *reinterpret_cast<uint32_t*>(&h1);
    lu.x = *reinterpret_cast<uint32_t*>(&l0);
    lu.y = *reinterpret_cast<uint32_t*>(&l1);
    *reinterpret_cast<uint2*>(hp) = hu;
    *reinterpret_cast<uint2*>(lp) = lu;
}

// Convert a float4 to 4 fp16 (single 8B store).
__device__ __forceinline__ void conv4h(float4 v, __half* p)
{
    __half2 h0, h1;
    h0.x = __float2half_rn(v.x); h0.y = __float2half_rn(v.y);
    h1.x = __float2half_rn(v.z); h1.y = __float2half_rn(v.w);
    uint2 hu;
    hu.x = *reinterpret_cast<uint32_t*>(&h0);
    hu.y = *reinterpret_cast<uint32_t*>(&h1);
    *reinterpret_cast<uint2*>(p) = hu;
}

// ===========================================================================
// Split kernels
// ===========================================================================
__global__ __launch_bounds__(256)
void split_rows_kernel(const float* __restrict__ in,
                       __half* __restrict__ hi,
                       __half* __restrict__ lo, int n4)
{
    int i = blockIdx.x * 256 + threadIdx.x;
    if (i >= n4) return;
    float4 v = reinterpret_cast<const float4*>(in)[i];
    split4h(v, hi + i * 4, lo + i * 4);
}

// Transpose + convert: in [K,N] fp32 -> out [N,K] fp16
__global__ __launch_bounds__(256)
void conv_T_kernel(const float* __restrict__ in,
                   __half* __restrict__ hi, int K, int N)
{
    __shared__ float t[32][33];
    int n0 = blockIdx.x * 32, k0 = blockIdx.y * 32;
    int tx = threadIdx.x & 31, ty = threadIdx.x >> 5;   // 32 x 8
#pragma unroll
    for (int i = 0; i < 4; i++)
        t[ty + 8 * i][tx] = in[(size_t)(k0 + ty + 8 * i) * N + n0 + tx];
    __syncthreads();
#pragma unroll
    for (int i = 0; i < 4; i++) {
        float v = t[tx][ty + 8 * i];
        hi[(size_t)(n0 + ty + 8 * i) * K + k0 + tx] = __float2half_rn(v);
    }
}

// ===========================================================================
// cp.async double-buffered HMMA GEMM (fp16, 2-pass):
// C[M,N] = (Ahi+Alo)[M,K] @ B[N,K]^T + bias[N]
// ===========================================================================
#define SPAD    40
#define TILE_E  (128 * SPAD)
#define STAGE_E (3 * TILE_E)          // Ahi, Alo, B
#define GEMM_SMEM_BYTES (2 * STAGE_E * 2)

__device__ __forceinline__ void gemm_issue_loads(
    const __half* __restrict__ Ahi, const __half* __restrict__ Alo,
    const __half* __restrict__ B,
    uint32_t sm_base, int stage, int row0, int col0, int kk, int K, int tid)
{
    const uint32_t st = sm_base + (uint32_t)stage * STAGE_E * 2;
#pragma unroll
    for (int u = 0; u < 2; u++) {
        int s  = tid + u * 256;
        int r  = s >> 2;
        int cg = (s & 3) * 8;
        size_t goffA = (size_t)(row0 + r) * K + kk + cg;
        size_t goffB = (size_t)(col0 + r) * K + kk + cg;
        uint32_t so = (uint32_t)(r * SPAD + cg) * 2;
        cp16(st + 0 * TILE_E * 2 + so, Ahi + goffA);
        cp16(st + 1 * TILE_E * 2 + so, Alo + goffA);
        cp16(st + 2 * TILE_E * 2 + so, B + goffB);
    }
}

__global__ __launch_bounds__(256, 2)
void gemm_hmma_async(const __half* __restrict__ Ahi,
                     const __half* __restrict__ Alo,
                     const __half* __restrict__ B,
                     const float* __restrict__ bias,
                     float* __restrict__ C, int M, int N, int K)
{
    extern __shared__ __half sm[];
    const uint32_t sm_base = smem_u32(sm);

    const int tid  = threadIdx.x;
    const int lane = tid & 31;
    const int warp = tid >> 5;
    const int row0 = blockIdx.y * 128;
    const int col0 = blockIdx.x * 128;
    const int warp_m = (warp & 3) * 32;
    const int warp_n = (warp >> 2) * 64;

    float acc[2][8][4];
#pragma unroll
    for (int i = 0; i < 2; i++)
#pragma unroll
        for (int j = 0; j < 8; j++)
#pragma unroll
            for (int r = 0; r < 4; r++) acc[i][j][r] = 0.0f;

    const int a_r = warp_m + (lane & 15);
    const int a_c = (lane >> 4) * 8;
    const int b_r = warp_n + (lane & 7) + (lane >> 4) * 8;
    const int b_c = ((lane >> 3) & 1) * 8;

    const int nch = K >> 5;

    gemm_issue_loads(Ahi, Alo, B, sm_base, 0, row0, col0, 0, K, tid);
    CP_COMMIT();

    for (int c = 0; c < nch; c++) {
        const int cur = c & 1;
        if (c + 1 < nch) {
            gemm_issue_loads(Ahi, Alo, B, sm_base, cur ^ 1,
                             row0, col0, (c + 1) << 5, K, tid);
            CP_COMMIT();
            CP_WAIT(1);
        } else {
            CP_WAIT(0);
        }
        __syncthreads();

        const __half* sAhi = sm + cur * STAGE_E + 0 * TILE_E;
        const __half* sAlo = sm + cur * STAGE_E + 1 * TILE_E;
        const __half* sB   = sm + cur * STAGE_E + 2 * TILE_E;

#pragma unroll
        for (int ks = 0; ks < 32; ks += 16) {
            uint32_t a_h[2][4], a_l[2][4];
            uint32_t b_f[8][2];
#pragma unroll
            for (int i = 0; i < 2; i++) {
                int el = (a_r + i * 16) * SPAD + ks + a_c;
                ldm_x4(a_h[i], smem_u32(sAhi + el));
                ldm_x4(a_l[i], smem_u32(sAlo + el));
            }
#pragma unroll
            for (int jj = 0; jj < 4; jj++) {
                int el = (b_r + jj * 16) * SPAD + ks + b_c;
                ldm_x4(&b_f[jj * 2][0], smem_u32(sB + el));
            }
#pragma unroll
            for (int i = 0; i < 2; i++)
#pragma unroll
                for (int j = 0; j < 8; j++)
                    mma_f16(acc[i][j], a_h[i], b_f[j]);
#pragma unroll
            for (int i = 0; i < 2; i++)
#pragma unroll
                for (int j = 0; j < 8; j++)
                    mma_f16(acc[i][j], a_l[i], b_f[j]);
        }
        __syncthreads();
    }

#pragma unroll
    for (int i = 0; i < 2; i++) {
#pragma unroll
        for (int j = 0; j < 8; j++) {
            int m = row0 + warp_m + i * 16 + (lane >> 2);
            int n = col0 + warp_n + j * 8 + (lane & 3) * 2;
            float2 bz = *reinterpret_cast<const float2*>(&bias[n]);
            float2 o0; o0.x = acc[i][j][0] + bz.x; o0.y = acc[i][j][1] + bz.y;
            float2 o1; o1.x = acc[i][j][2] + bz.x; o1.y = acc[i][j][3] + bz.y;
            *reinterpret_cast<float2*>(&C[(size_t)m * N + n]) = o0;
            *reinterpret_cast<float2*>(&C[(size_t)(m + 8) * N + n]) = o1;
        }
    }
}

// ===========================================================================
// Scores on HMMA (fp16 2-pass): W[bh,q,k] = (Q.K)/8, masked values = -10000.
// Lower-triangle tiles only; heavy (high-qt) tiles launched first.
// ===========================================================================
#define MASKED_BIAS -10000.0f

__global__ __launch_bounds__(256)
void scores_hmma_kernel(float* __restrict__ W)
{
    __shared__ __half sQh[128 * SPAD];
    __shared__ __half sQl[128 * SPAD];
    __shared__ __half sKh[128 * SPAD];

    const int tid  = threadIdx.x;
    const int lane = tid & 31;
    const int warp = tid >> 5;
    const int bh   = blockIdx.y;
    const int b    = bh >> 4;
    const int h    = bh & 15;

    int pair = 135 - blockIdx.x;          // heavy (high-qt) tiles first
    int qt = (int)((-1.0f + sqrtf(1.0f + 8.0f * (float)pair)) * 0.5f);
    while ((qt + 1) * (qt + 2) / 2 <= pair) ++qt;
    while (qt * (qt + 1) / 2 > pair) --qt;
    const int kt = pair - qt * (qt + 1) / 2;

    const int q0 = qt * 128;
    const int k0 = kt * 128;
    const int warp_m = (warp & 3) * 32;
    const int warp_n = (warp >> 2) * 64;

    float acc[2][8][4];
#pragma unroll
    for (int i = 0; i < 2; i++)
#pragma unroll
        for (int j = 0; j < 8; j++)
#pragma unroll
            for (int r = 0; r < 4; r++) acc[i][j][r] = 0.0f;

    const int a_r = warp_m + (lane & 15);
    const int a_c = (lane >> 4) * 8;
    const int b_r = warp_n + (lane & 7) + (lane >> 4) * 8;
    const int b_c = ((lane >> 3) & 1) * 8;

    const size_t qbase = (size_t)(b * S_ + q0) * QKV_N + h * DH_;
    const size_t kbase = (size_t)(b * S_ + k0) * QKV_N + D_ + h * DH_;

    const int lr = tid >> 1;
    const int lc0 = (tid & 1) * 16;

    for (int dc = 0; dc < DH_; dc += 32) {
#pragma unroll
        for (int i = 0; i < 4; i++) {
            int c = lc0 + i * 4;
            float4 vq = *reinterpret_cast<const float4*>(
                &g_qkv[qbase + (size_t)lr * QKV_N + dc + c]);
            float4 vk = *reinterpret_cast<const float4*>(
                &g_qkv[kbase + (size_t)lr * QKV_N + dc + c]);
            split4h(vq, &sQh[lr * SPAD + c], &sQl[lr * SPAD + c]);
            conv4h(vk, &sKh[lr * SPAD + c]);
        }
        __syncthreads();

#pragma unroll
        for (int ks = 0; ks < 32; ks += 16) {
            uint32_t a_h[2][4], a_l[2][4];
            uint32_t b_f[8][2];
#pragma unroll
            for (int i = 0; i < 2; i++) {
                int el = (a_r + i * 16) * SPAD + ks + a_c;
                ldm_x4(a_h[i], smem_u32(&sQh[el]));
                ldm_x4(a_l[i], smem_u32(&sQl[el]));
            }
#pragma unroll
            for (int jj = 0; jj < 4; jj++) {
                int el = (b_r + jj * 16) * SPAD + ks + b_c;
                ldm_x4(&b_f[jj * 2][0], smem_u32(&sKh[el]));
            }
#pragma unroll
            for (int i = 0; i < 2; i++)
#pragma unroll
                for (int j = 0; j < 8; j++)
                    mma_f16(acc[i][j], a_h[i], b_f[j]);
#pragma unroll
            for (int i = 0; i < 2; i++)
#pragma unroll
                for (int j = 0; j < 8; j++)
                    mma_f16(acc[i][j], a_l[i], b_f[j]);
        }
        __syncthreads();
    }

    float* Wbh = W + (size_t)bh * S_ * S_;
#pragma unroll
    for (int i = 0; i < 2; i++) {
#pragma unroll
        for (int j = 0; j < 8; j++) {
            int q  = q0 + warp_m + i * 16 + (lane >> 2);
            int k  = k0 + warp_n + j * 8 + (lane & 3) * 2;
            float2 o0, o1;
            o0.x = (k     > q) ? MASKED_BIAS : acc[i][j][0] * 0.125f;
            o0.y = (k + 1 > q) ? MASKED_BIAS : acc[i][j][1] * 0.125f;
            o1.x = (k     > q + 8) ? MASKED_BIAS : acc[i][j][2] * 0.125f;
            o1.y = (k + 1 > q + 8) ? MASKED_BIAS : acc[i][j][3] * 0.125f;
            *reinterpret_cast<float2*>(&Wbh[(size_t)q * S_ + k]) = o0;
            *reinterpret_cast<float2*>(&Wbh[(size_t)(q + 8) * S_ + k]) = o1;
        }
    }
}

// ---------------------------------------------------------------------------
// Softmax in place: float4 IO, warp-shuffle reductions, __expf.
// Masked-region float4 loads skipped; all stores written (zeros included).
// ---------------------------------------------------------------------------
__global__ __launch_bounds__(256)
void softmax_kernel(float* __restrict__ W)
{
    const int tid = threadIdx.x;
    const int lane = tid & 31;
    const int warp = tid >> 5;
    const int row = blockIdx.x;
    const int q = row & (S_ - 1);
    const int nvalid = q + 1;
    float* w = W + (size_t)row * S_;

    __shared__ float red[8];

    float4 v[2];
    float m = -1e30f;
#pragma unroll
    for (int r = 0; r < 2; r++) {
        int k0 = (r * 256 + tid) * 4;
        float4 x;
        if (k0 < nvalid) {
            x = *reinterpret_cast<const float4*>(w + k0);
            x.x = (k0 + 0 < nvalid) ? x.x : -1e30f;
            x.y = (k0 + 1 < nvalid) ? x.y : -1e30f;
            x.z = (k0 + 2 < nvalid) ? x.z : -1e30f;
            x.w = (k0 + 3 < nvalid) ? x.w : -1e30f;
        } else {
            x.x = x.y = x.z = x.w = -1e30f;
        }
        v[r] = x;
        m = fmaxf(m, fmaxf(fmaxf(x.x, x.y), fmaxf(x.z, x.w)));
    }
#pragma unroll
    for (int off = 16; off > 0; off >>= 1)
        m = fmaxf(m, __shfl_xor_sync(0xFFFFFFFFu, m, off));
    if (lane == 0) red[warp] = m;
    __syncthreads();
    float mx = red[0];
#pragma unroll
    for (int i = 1; i < 8; i++) mx = fmaxf(mx, red[i]);
    __syncthreads();

    float s = 0.0f;
#pragma unroll
    for (int r = 0; r < 2; r++) {
        int k0 = (r * 256 + tid) * 4;
        float4 x = v[r];
        x.x = (k0 + 0 < nvalid) ? __expf(x.x - mx) : 0.0f;
        x.y = (k0 + 1 < nvalid) ? __expf(x.y - mx) : 0.0f;
        x.z = (k0 + 2 < nvalid) ? __expf(x.z - mx) : 0.0f;
        x.w = (k0 + 3 < nvalid) ? __expf(x.w - mx) : 0.0f;
        v[r] = x;
        s += x.x + x.y + x.z + x.w;
    }
#pragma unroll
    for (int off = 16; off > 0; off >>= 1)
        s += __shfl_xor_sync(0xFFFFFFFFu, s, off);
    if (lane == 0) red[warp] = s;
    __syncthreads();
    float tot = red[0];
#pragma unroll
    for (int i = 1; i < 8; i++) tot += red[i];
    const float inv = 1.0f / tot;

#pragma unroll
    for (int r = 0; r < 2; r++) {
        int k0 = (r * 256 + tid) * 4;
        float4 x = v[r];
        x.x *= inv; x.y *= inv; x.z *= inv; x.w *= inv;
        *reinterpret_cast<float4*>(w + k0) = x;
    }
}

// ===========================================================================
// AV on HMMA (fp16 2-pass): attn = softmax(W) @ V, causal chunk range.
// Heavy q-blocks launched first. Epilogue writes fp16 hi/lo into g_ahi/g_alo.
// ===========================================================================
__global__ __launch_bounds__(256)
void av_hmma_kernel(const float* __restrict__ W)
{
    __shared__ __half sWh[128 * SPAD];
    __shared__ __half sWl[128 * SPAD];
    __shared__ __half sVh[64 * SPAD];

    const int tid  = threadIdx.x;
    const int lane = tid & 31;
    const int warp = tid >> 5;
    const int bh   = blockIdx.y;
    const int b    = bh >> 4;
    const int h    = bh & 15;
    const int qblk = 15 - blockIdx.x;      // heavy blocks first
    const int q0   = qblk * 128;
    const int warp_m = warp * 16;

    const float* Wbh = W + (size_t)bh * S_ * S_;
    const size_t vbase = (size_t)b * S_ * QKV_N + 2 * D_ + h * DH_;

    float acc[8][4];
#pragma unroll
    for (int j = 0; j < 8; j++)
#pragma unroll
        for (int r = 0; r < 4; r++) acc[j][r] = 0.0f;

    const int a_r = warp_m + (lane & 15);
    const int a_c = (lane >> 4) * 8;
    const int b_r = (lane & 7) + (lane >> 4) * 8;
    const int b_c = ((lane >> 3) & 1) * 8;

    const int wr  = tid >> 1;
    const int wc0 = (tid & 1) * 16;
    const int vd  = tid & 63;
    const int vk0 = (tid >> 6) * 8;

    const int nch = (qblk + 1) * 4;
    for (int t = 0; t < nch; t++) {
        const int kc = t * 32;
#pragma unroll
        for (int i = 0; i < 4; i++) {
            int c = wc0 + i * 4;
            float4 v = *reinterpret_cast<const float4*>(
                &Wbh[(size_t)(q0 + wr) * S_ + kc + c]);
            split4h(v, &sWh[wr * SPAD + c], &sWl[wr * SPAD + c]);
        }
        {
            uint32_t hp[4];
#pragma unroll
            for (int i = 0; i < 4; i++) {
                float x0 = g_qkv[vbase + (size_t)(kc + vk0 + 2 * i) * QKV_N + vd];
                float x1 = g_qkv[vbase + (size_t)(kc + vk0 + 2 * i + 1) * QKV_N + vd];
                __half2 hh;
                hh.x = __float2half_rn(x0); hh.y = __float2half_rn(x1);
                hp[i] = *reinterpret_cast<uint32_t*>(&hh);
            }
            uint4 hv; hv.x = hp[0]; hv.y = hp[1]; hv.z = hp[2]; hv.w = hp[3];
            *reinterpret_cast<uint4*>(&sVh[vd * SPAD + vk0]) = hv;
        }
        __syncthreads();

#pragma unroll
        for (int ks = 0; ks < 32; ks += 16) {
            uint32_t a_h[4], a_l[4];
            uint32_t b_f[8][2];
            {
                int el = a_r * SPAD + ks + a_c;
                ldm_x4(a_h, smem_u32(&sWh[el]));
                ldm_x4(a_l, smem_u32(&sWl[el]));
            }
#pragma unroll
            for (int jj = 0; jj < 4; jj++) {
                int el = (b_r + jj * 16) * SPAD + ks + b_c;
                ldm_x4(&b_f[jj * 2][0], smem_u32(&sVh[el]));
            }
#pragma unroll
            for (int j = 0; j < 8; j++)
                mma_f16(acc[j], a_h, b_f[j]);
#pragma unroll
            for (int j = 0; j < 8; j++)
                mma_f16(acc[j], a_l, b_f[j]);
        }
        __syncthreads();
    }

    // epilogue: split to fp16 hi/lo and write g_ahi/g_alo directly
#pragma unroll
    for (int j = 0; j < 8; j++) {
        int m = q0 + warp_m + (lane >> 2);
        int n = j * 8 + (lane & 3) * 2;
        size_t o0 = (size_t)(b * S_ + m) * D_ + h * DH_ + n;
        size_t o1 = (size_t)(b * S_ + m + 8) * D_ + h * DH_ + n;
        __half2 h0, l0, h1, l1;
        h0.x = __float2half_rn(acc[j][0]);
        h0.y = __float2half_rn(acc[j][1]);
        l0.x = __float2half_rn(acc[j][0] - __half2float(h0.x));
        l0.y = __float2half_rn(acc[j][1] - __half2float(h0.y));
        h1.x = __float2half_rn(acc[j][2]);
        h1.y = __float2half_rn(acc[j][3]);
        l1.x = __float2half_rn(acc[j][2] - __half2float(h1.x));
        l1.y = __float2half_rn(acc[j][3] - __half2float(h1.y));
        *reinterpret_cast<__half2*>(&g_ahi[o0]) = h0;
        *reinterpret_cast<__half2*>(&g_alo[o0]) = l0;
        *reinterpret_cast<__half2*>(&g_ahi[o1]) = h1;
        *reinterpret_cast<__half2*>(&g_alo[o1]) = l1;
    }
}

// ---------------------------------------------------------------------------
extern "C" void kernel_launch(void* const* d_in, const int* in_sizes, int n_in,
                              void* d_out, int out_size)
{
    const float* hs       = (const float*)d_in[0];
    const float* c_attn_w = (const float*)d_in[1];
    const float* c_attn_b = (const float*)d_in[2];
    const float* c_proj_w = (const float*)d_in[3];
    const float* c_proj_b = (const float*)d_in[4];

    float* out  = (float*)d_out;
    float* Wout = out + OUT_ATTN_ELEMS;

    float *qkv_ptr = nullptr;
    __half *ahi, *alo, *w1h, *w2h;
    cudaGetSymbolAddress((void**)&qkv_ptr, g_qkv);
    cudaGetSymbolAddress((void**)&ahi, g_ahi);
    cudaGetSymbolAddress((void**)&alo, g_alo);
    cudaGetSymbolAddress((void**)&w1h, g_w1h);
    cudaGetSymbolAddress((void**)&w2h, g_w2h);

    static bool attr_set = false;
    if (!attr_set) {
        cudaFuncSetAttribute(gemm_hmma_async,
                             cudaFuncAttributeMaxDynamicSharedMemorySize,
                             GEMM_SMEM_BYTES);
        attr_set = true;
    }

    // 0) splits/conversions for dense GEMMs
    split_rows_kernel<<<(BS_ * D_ / 4 + 255) / 256, 256>>>(hs, ahi, alo, BS_ * D_ / 4);
    conv_T_kernel<<<dim3(QKV_N / 32, D_ / 32), 256>>>(c_attn_w, w1h, D_, QKV_N);
    conv_T_kernel<<<dim3(D_ / 32, D_ / 32), 256>>>(c_proj_w, w2h, D_, D_);

    // 1) QKV GEMM (HMMA fp16 2-pass, cp.async pipelined)
    gemm_hmma_async<<<dim3(QKV_N / 128, BS_ / 128), 256, GEMM_SMEM_BYTES>>>(
        ahi, alo, w1h, c_attn_b, qkv_ptr, BS_, QKV_N, D_);

    // 2) Scores (HMMA fp16 2-pass, lower-triangle tiles, heavy-first)
    scores_hmma_kernel<<<dim3(136, B_ * H_), 256>>>(Wout);

    // 3) Softmax in place (masked-region reads skipped)
    softmax_kernel<<<B_ * H_ * S_, 256>>>(Wout);

    // 4) AV (HMMA fp16 2-pass, heavy-first) -> writes g_ahi/g_alo directly
    av_hmma_kernel<<<dim3(S_ / 128, B_ * H_), 256>>>(Wout);

    // 5) proj GEMM (HMMA fp16 2-pass) — consumes g_ahi/g_alo from AV
    gemm_hmma_async<<<dim3(D_ / 128, BS_ / 128), 256, GEMM_SMEM_BYTES>>>(
        ahi, alo, w2h, c_proj_b, out, BS_, D_, D_);
}